// round 16
// baseline (speedup 1.0000x reference)
#include <cuda_runtime.h>
#include <cuda_fp16.h>
#include <stdint.h>
#include <math.h>

constexpr int I_SZ = 256, D_SZ = 128, HD = 32768, MB = 64;
// K extended to 144: [0,128) = hidden dims, 128 = x*W term, 129 = bias, 130-143 = 0
constexpr int NKS   = 9;                     // 9 k-steps of 16
constexpr int ROWB  = 304;                   // 144 halfs = 288 B + 16 pad (19*16, odd -> conflict-free)
constexpr int SROWB = 288;                   // scratch row bytes (18 chunks of 16B)
constexpr uint32_t A_PLANE = 64 * ROWB;      // 19456 B
constexpr uint32_t U_PLANE = 128 * ROWB;     // 38912 B
constexpr uint32_t SM_A = 0;
constexpr uint32_t SM_U = A_PLANE;
constexpr uint32_t SMEM_MAIN = SM_A + A_PLANE + U_PLANE + 256;  // 58624 -> 3 CTAs/SM

// U scratch: [gate z/r/h][group] -> [n=128][288B]: k<128 data, k128=W, k129=b, rest 0
__device__ __align__(256) unsigned char g_Uscr[3ull * 256 * 128 * SROWB];

__device__ __forceinline__ uint32_t smem_u32(const void* p) {
    uint32_t a;
    asm("{ .reg .u64 t; cvta.to.shared.u64 t, %1; cvt.u32.u64 %0, t; }" : "=r"(a) : "l"(p));
    return a;
}
#define CP16(dst, src) asm volatile("cp.async.cg.shared.global [%0], [%1], 16;" :: "r"(dst), "l"(src))
#define CP_COMMIT()    asm volatile("cp.async.commit_group;" ::: "memory")
#define CP_WAIT(n)     asm volatile("cp.async.wait_group %0;" :: "n"(n) : "memory")
#define LDSM4(R, addr)                                                          \
    asm volatile("ldmatrix.sync.aligned.m8n8.x4.shared.b16 {%0,%1,%2,%3}, [%4];"\
        : "=r"((R)[0]), "=r"((R)[1]), "=r"((R)[2]), "=r"((R)[3]) : "r"(addr))
#define MMA16816(c, a0, a1, a2, a3, b0, b1)                                     \
    asm volatile("mma.sync.aligned.m16n8k16.row.col.f32.f16.f16.f32 "           \
        "{%0,%1,%2,%3}, {%4,%5,%6,%7}, {%8,%9}, {%0,%1,%2,%3};"                 \
        : "+f"((c)[0]), "+f"((c)[1]), "+f"((c)[2]), "+f"((c)[3])                \
        : "r"(a0), "r"(a1), "r"(a2), "r"(a3), "r"(b0), "r"(b1))

__device__ __forceinline__ float tanha(float x) {
    float y;
    asm("tanh.approx.f32 %0, %1;" : "=f"(y) : "f"(x));
    return y;
}
__device__ __forceinline__ float sigf(float x) {      // sigmoid = 0.5 + 0.5*tanh(x/2)
    return fmaf(tanha(0.5f * x), 0.5f, 0.5f);
}
__device__ __forceinline__ uint32_t packh(float a, float b) {
    __half2 t = __floats2half2_rn(a, b);
    return *(uint32_t*)&t;
}

// ---------- prep: U[i][k][n] -> B[n][k] fp16 + embedded W/b columns ----------
__global__ __launch_bounds__(256) void gru_prep(
    const float* __restrict__ Uz, const float* __restrict__ Ur, const float* __restrict__ Uh,
    const float* __restrict__ Wz, const float* __restrict__ Wr, const float* __restrict__ Wh,
    const float* __restrict__ bz, const float* __restrict__ br, const float* __restrict__ bh) {
    extern __shared__ float sf[];  // [128][129]
    const int i = blockIdx.x, g = blockIdx.y, tid = threadIdx.x;
    const float* Ui = ((g == 0) ? Uz : (g == 1) ? Ur : Uh) + (size_t)i * D_SZ * D_SZ;
    const float* W  = ((g == 0) ? Wz : (g == 1) ? Wr : Wh) + (size_t)i * D_SZ;
    const float* bb = ((g == 0) ? bz : (g == 1) ? br : bh) + (size_t)i * D_SZ;
    const float4* u4 = (const float4*)Ui;
#pragma unroll 4
    for (int t = tid; t < 4096; t += 256) {
        int row = t >> 5, c4 = (t & 31) * 4;
        float4 v = u4[t];
        float* dst = sf + row * 129 + c4;
        dst[0] = v.x; dst[1] = v.y; dst[2] = v.z; dst[3] = v.w;
    }
    __syncthreads();
    unsigned char* hp = g_Uscr + (size_t)(g * 256 + i) * (128 * SROWB);
    for (int c = tid; c < 2048; c += 256) {            // k<128 body
        int n = c >> 4, k0 = (c & 15) * 8;
        uint32_t hw[4];
#pragma unroll
        for (int j = 0; j < 4; j++) {
            __half h0 = __float2half_rn(sf[(k0 + 2 * j) * 129 + n]);      // B[n][k]=U[k][n]
            __half h1 = __float2half_rn(sf[(k0 + 2 * j + 1) * 129 + n]);
            hw[j] = (uint32_t)__half_as_ushort(h0) | ((uint32_t)__half_as_ushort(h1) << 16);
        }
        *(uint4*)(hp + n * SROWB + k0 * 2) = make_uint4(hw[0], hw[1], hw[2], hw[3]);
    }
    if (tid < 128) {                                   // tail chunks 16,17
        int n = tid;
        *(uint4*)(hp + n * SROWB + 256) = make_uint4(packh(W[n], bb[n]), 0u, 0u, 0u);
        *(uint4*)(hp + n * SROWB + 272) = make_uint4(0u, 0u, 0u, 0u);
    }
}

// cp.async one U gate (36KB) into the smem U buffer
__device__ __forceinline__ void cp_u(uint32_t dst, const unsigned char* src, int tid) {
    for (int t = tid; t < 2304; t += 256) {
        uint32_t row = (uint32_t)t / 18u, c = (uint32_t)t - row * 18u;
        CP16(dst + row * ROWB + c * 16, src + row * SROWB + c * 16);
    }
    CP_COMMIT();
}

// GEMM: acc += A * U  (warp tile M=32, N=32, K=144; 72 MMAs)
__device__ __forceinline__ void gemm1(uint32_t sb, int warp_m, int warp_n,
                                      uint32_t offA, uint32_t offB, float acc[2][4][4]) {
#pragma unroll
    for (int mi = 0; mi < 2; mi++)
#pragma unroll
        for (int ni = 0; ni < 4; ni++)
#pragma unroll
            for (int q = 0; q < 4; q++) acc[mi][ni][q] = 0.0f;
#pragma unroll
    for (int ks = 0; ks < NKS; ks++) {
        const uint32_t kb = ks * 32;
        uint32_t A[2][4], B[2][4];
#pragma unroll
        for (int mi = 0; mi < 2; mi++)
            LDSM4(A[mi], sb + SM_A + (warp_m + mi * 16) * ROWB + kb + offA);
#pragma unroll
        for (int nj = 0; nj < 2; nj++)
            LDSM4(B[nj], sb + SM_U + (warp_n + nj * 16) * ROWB + kb + offB);
#pragma unroll
        for (int mi = 0; mi < 2; mi++)
#pragma unroll
            for (int nj = 0; nj < 2; nj++)
#pragma unroll
                for (int hh = 0; hh < 2; hh++)
                    MMA16816(acc[mi][nj * 2 + hh],
                             A[mi][0], A[mi][1], A[mi][2], A[mi][3],
                             B[nj][hh * 2], B[nj][hh * 2 + 1]);
    }
}

// ---------- main: M=64/CTA, affine terms in-GEMM, 3 CTAs/SM ----------
__global__ __launch_bounds__(256, 3) void gru_main(
    const float* __restrict__ X, const float* __restrict__ hs,
    float* __restrict__ out_hnew, float* __restrict__ out_ht) {
    extern __shared__ __align__(16) unsigned char smem[];
    const uint32_t sb = smem_u32(smem);
    const int tid = threadIdx.x, warp = tid >> 5, l = tid & 31;
    const int i = blockIdx.y, b0 = blockIdx.x * MB;

    const unsigned char* uz = g_Uscr + (size_t)(0 * 256 + i) * (128 * SROWB);
    const unsigned char* ur = g_Uscr + (size_t)(1 * 256 + i) * (128 * SROWB);
    const unsigned char* uh = g_Uscr + (size_t)(2 * 256 + i) * (128 * SROWB);
    cp_u(sb + SM_U, uz, tid);

    // A <= fp16(hg) | x | 1 | 0-pad    (64 rows x 18 chunks)
    for (int c = tid; c < 1152; c += 256) {
        uint32_t row = (uint32_t)c / 18u, ch = (uint32_t)c - row * 18u;
        uint32_t dst = sb + SM_A + row * ROWB + ch * 16;
        if (ch < 16) {
            int k0 = ch * 8;
            const float4* g = (const float4*)(hs + (size_t)(b0 + row) * HD +
                                              (size_t)i * D_SZ + k0);
            float4 v0 = g[0], v1 = g[1];
            uint4 o = make_uint4(packh(v0.x, v0.y), packh(v0.z, v0.w),
                                 packh(v1.x, v1.y), packh(v1.z, v1.w));
            *(uint4*)(smem + SM_A + row * ROWB + ch * 16) = o;
        } else if (ch == 16) {
            float xv = X[(size_t)(b0 + row) * I_SZ + i];
            *(uint4*)(smem + SM_A + row * ROWB + 256) =
                make_uint4(packh(xv, 1.0f), 0u, 0u, 0u);
        } else {
            *(uint4*)(smem + SM_A + row * ROWB + 272) = make_uint4(0u, 0u, 0u, 0u);
        }
        (void)dst;
    }
    CP_WAIT(0);
    __syncthreads();             // [1] A + Uz resident

    const int warp_m = (warp & 1) * 32, warp_n = (warp >> 1) * 32;
    const uint32_t offA = (uint32_t)((l & 15) * ROWB + (l >> 4) * 16);
    const uint32_t offB = (uint32_t)((l & 7) * ROWB + ((l >> 4) & 1) * (8 * ROWB) +
                                     ((l >> 3) & 1) * 16);
    float acc[2][4][4];
    half2 z2[2][4][2];           // z gate packed fp16 (8 regs)

    // ---- z gate ----
    gemm1(sb, warp_m, warp_n, offA, offB, acc);
    __syncthreads();             // [2] Uz reads done
    cp_u(sb + SM_U, ur, tid);    // Ur -> U, overlaps z epilogue
#pragma unroll
    for (int mi = 0; mi < 2; mi++)
#pragma unroll
        for (int j = 0; j < 4; j++)
#pragma unroll
            for (int rr = 0; rr < 2; rr++)
                z2[mi][j][rr] = __floats2half2_rn(sigf(acc[mi][j][rr * 2]),
                                                  sigf(acc[mi][j][rr * 2 + 1]));
    CP_WAIT(0);
    __syncthreads();             // [3] Ur resident

    // ---- r gate ----
    gemm1(sb, warp_m, warp_n, offA, offB, acc);
    __syncthreads();             // [4] Ur + A reads done
    cp_u(sb + SM_U, uh, tid);    // Uh -> U, overlaps r epilogue
#pragma unroll
    for (int mi = 0; mi < 2; mi++)
#pragma unroll
        for (int j = 0; j < 4; j++) {
            int col = warp_n + j * 8 + (l & 3) * 2;
#pragma unroll
            for (int rr = 0; rr < 2; rr++) {
                int row = warp_m + mi * 16 + rr * 8 + (l >> 2);
                half2* pA = (half2*)(smem + SM_A + row * ROWB + col * 2);
                half2 hg2 = *pA;
                float r0 = sigf(acc[mi][j][rr * 2]);
                float r1 = sigf(acc[mi][j][rr * 2 + 1]);
                *pA = __halves2half2(
                    __float2half_rn(r0 * __half2float(__low2half(hg2))),
                    __float2half_rn(r1 * __half2float(__high2half(hg2))));
            }
        }
    CP_WAIT(0);
    __syncthreads();             // [5] Uh + rh plane ready (x,1 cols untouched)

    // ---- h gate + fused combine (tail: global hg via __ldg, no barrier) ----
    gemm1(sb, warp_m, warp_n, offA, offB, acc);
#pragma unroll
    for (int mi = 0; mi < 2; mi++)
#pragma unroll
        for (int j = 0; j < 4; j++) {
            int col = warp_n + j * 8 + (l & 3) * 2;
#pragma unroll
            for (int rr = 0; rr < 2; rr++) {
                int row = warp_m + mi * 16 + rr * 8 + (l >> 2);
                size_t gidx = (size_t)(b0 + row) * HD + (size_t)i * D_SZ + col;
                float2 hg = __ldg((const float2*)(hs + gidx));
                float t0 = tanha(acc[mi][j][rr * 2]);
                float t1 = tanha(acc[mi][j][rr * 2 + 1]);
                float z0 = __half2float(__low2half(z2[mi][j][rr]));
                float z1 = __half2float(__high2half(z2[mi][j][rr]));
                *(float2*)(out_ht + gidx)   = make_float2(t0, t1);
                *(float2*)(out_hnew + gidx) = make_float2(z0 * hg.x + (1.0f - z0) * t0,
                                                          z1 * hg.y + (1.0f - z1) * t1);
            }
        }
}

extern "C" void kernel_launch(void* const* d_in, const int* in_sizes, int n_in,
                              void* d_out, int out_size) {
    const float* X  = (const float*)d_in[0];
    const float* h  = (const float*)d_in[1];
    const float* Wr = (const float*)d_in[2];
    const float* Wz = (const float*)d_in[3];
    const float* Wh = (const float*)d_in[4];
    const float* Ur = (const float*)d_in[5];
    const float* Uz = (const float*)d_in[6];
    const float* Uh = (const float*)d_in[7];
    const float* br = (const float*)d_in[8];
    const float* bz = (const float*)d_in[9];
    const float* bh = (const float*)d_in[10];
    float* out = (float*)d_out;
    float* out_hnew = out;
    float* out_ht   = out + (size_t)1024 * HD;

    cudaFuncSetAttribute(gru_prep, cudaFuncAttributeMaxDynamicSharedMemorySize, 128 * 129 * 4);
    cudaFuncSetAttribute(gru_main, cudaFuncAttributeMaxDynamicSharedMemorySize, (int)SMEM_MAIN);

    gru_prep<<<dim3(256, 3), 256, 128 * 129 * 4>>>(Uz, Ur, Uh, Wz, Wr, Wh, bz, br, bh);
    gru_main<<<dim3(16, 256), 256, SMEM_MAIN>>>(X, h, out_hnew, out_ht);
}

// round 17
// speedup vs baseline: 1.0020x; 1.0020x over previous
#include <cuda_runtime.h>
#include <cuda_fp16.h>
#include <stdint.h>
#include <math.h>

constexpr int I_SZ = 256, D_SZ = 128, HD = 32768, MB = 64;
// K extended to 144: [0,128) = hidden dims, 128 = x (A) / W (B), 129 = 1 (A) / b (B), 130-143 = 0
constexpr int NKS   = 9;                     // 9 k-steps of 16
constexpr int ROWB  = 304;                   // 144 halfs = 288 B + 16 pad (19*16, odd -> conflict-free)
constexpr int SROWB = 288;                   // scratch row bytes (18 chunks of 16B)
constexpr uint32_t A_PLANE = 64 * ROWB;      // 19456 B
constexpr uint32_t U_PLANE = 128 * ROWB;     // 38912 B
constexpr uint32_t SM_A = 0;
constexpr uint32_t SM_U = A_PLANE;
constexpr uint32_t SMEM_MAIN = SM_A + A_PLANE + U_PLANE + 256;  // 58624 -> 3 CTAs/SM

// U scratch: [gate z/r/h][group] -> [n=128][288B]: k<128 data, k128=W, k129=b, rest 0
__device__ __align__(256) unsigned char g_Uscr[3ull * 256 * 128 * SROWB];

__device__ __forceinline__ uint32_t smem_u32(const void* p) {
    uint32_t a;
    asm("{ .reg .u64 t; cvta.to.shared.u64 t, %1; cvt.u32.u64 %0, t; }" : "=r"(a) : "l"(p));
    return a;
}
#define CP16(dst, src) asm volatile("cp.async.cg.shared.global [%0], [%1], 16;" :: "r"(dst), "l"(src))
#define CP_COMMIT()    asm volatile("cp.async.commit_group;" ::: "memory")
#define CP_WAIT(n)     asm volatile("cp.async.wait_group %0;" :: "n"(n) : "memory")
#define LDSM4(R, addr)                                                          \
    asm volatile("ldmatrix.sync.aligned.m8n8.x4.shared.b16 {%0,%1,%2,%3}, [%4];"\
        : "=r"((R)[0]), "=r"((R)[1]), "=r"((R)[2]), "=r"((R)[3]) : "r"(addr))
#define MMA16816(c, a0, a1, a2, a3, b0, b1)                                     \
    asm volatile("mma.sync.aligned.m16n8k16.row.col.f32.f16.f16.f32 "           \
        "{%0,%1,%2,%3}, {%4,%5,%6,%7}, {%8,%9}, {%0,%1,%2,%3};"                 \
        : "+f"((c)[0]), "+f"((c)[1]), "+f"((c)[2]), "+f"((c)[3])                \
        : "r"(a0), "r"(a1), "r"(a2), "r"(a3), "r"(b0), "r"(b1))

__device__ __forceinline__ float tanha(float x) {
    float y;
    asm("tanh.approx.f32 %0, %1;" : "=f"(y) : "f"(x));
    return y;
}
__device__ __forceinline__ float sigf(float x) {      // sigmoid = 0.5 + 0.5*tanh(x/2)
    return fmaf(tanha(0.5f * x), 0.5f, 0.5f);
}
__device__ __forceinline__ uint32_t packh(float a, float b) {
    __half2 t = __floats2half2_rn(a, b);
    return *(uint32_t*)&t;
}

// ---------- prep: U[i][k][n] -> B[n][k] fp16 + embedded W/b columns ----------
__global__ __launch_bounds__(256) void gru_prep(
    const float* __restrict__ Uz, const float* __restrict__ Ur, const float* __restrict__ Uh,
    const float* __restrict__ Wz, const float* __restrict__ Wr, const float* __restrict__ Wh,
    const float* __restrict__ bz, const float* __restrict__ br, const float* __restrict__ bh) {
    extern __shared__ float sf[];  // [128][129]
    const int i = blockIdx.x, g = blockIdx.y, tid = threadIdx.x;
    const float* Ui = ((g == 0) ? Uz : (g == 1) ? Ur : Uh) + (size_t)i * D_SZ * D_SZ;
    const float* W  = ((g == 0) ? Wz : (g == 1) ? Wr : Wh) + (size_t)i * D_SZ;
    const float* bb = ((g == 0) ? bz : (g == 1) ? br : bh) + (size_t)i * D_SZ;
    const float4* u4 = (const float4*)Ui;
#pragma unroll 4
    for (int t = tid; t < 4096; t += 256) {
        int row = t >> 5, c4 = (t & 31) * 4;
        float4 v = u4[t];
        float* dst = sf + row * 129 + c4;
        dst[0] = v.x; dst[1] = v.y; dst[2] = v.z; dst[3] = v.w;
    }
    __syncthreads();
    unsigned char* hp = g_Uscr + (size_t)(g * 256 + i) * (128 * SROWB);
    for (int c = tid; c < 2048; c += 256) {            // k<128 body
        int n = c >> 4, k0 = (c & 15) * 8;
        uint32_t hw[4];
#pragma unroll
        for (int j = 0; j < 4; j++) {
            __half h0 = __float2half_rn(sf[(k0 + 2 * j) * 129 + n]);      // B[n][k]=U[k][n]
            __half h1 = __float2half_rn(sf[(k0 + 2 * j + 1) * 129 + n]);
            hw[j] = (uint32_t)__half_as_ushort(h0) | ((uint32_t)__half_as_ushort(h1) << 16);
        }
        *(uint4*)(hp + n * SROWB + k0 * 2) = make_uint4(hw[0], hw[1], hw[2], hw[3]);
    }
    if (tid < 128) {                                   // tail chunks 16,17
        int n = tid;
        *(uint4*)(hp + n * SROWB + 256) = make_uint4(packh(W[n], bb[n]), 0u, 0u, 0u);
        *(uint4*)(hp + n * SROWB + 272) = make_uint4(0u, 0u, 0u, 0u);
    }
}

// cp.async one U gate (36KB): power-of-2 body + tail, shifts only
__device__ __forceinline__ void cp_u(uint32_t dst, const unsigned char* src, int tid) {
#pragma unroll
    for (int t = tid; t < 2048; t += 256) {            // chunks 0-15 of every row
        uint32_t row = (uint32_t)t >> 4, c = (uint32_t)t & 15u;
        CP16(dst + row * ROWB + c * 16, src + row * SROWB + c * 16);
    }
    {                                                  // chunks 16,17
        uint32_t row = (uint32_t)tid >> 1, c = 16u + ((uint32_t)tid & 1u);
        CP16(dst + row * ROWB + c * 16, src + row * SROWB + c * 16);
    }
    CP_COMMIT();
}

// GEMM: acc += A * U  (warp tile M=32, N=32, K=144; 72 MMAs)
__device__ __forceinline__ void gemm1(uint32_t sb, int warp_m, int warp_n,
                                      uint32_t offA, uint32_t offB, float acc[2][4][4]) {
#pragma unroll
    for (int mi = 0; mi < 2; mi++)
#pragma unroll
        for (int ni = 0; ni < 4; ni++)
#pragma unroll
            for (int q = 0; q < 4; q++) acc[mi][ni][q] = 0.0f;
#pragma unroll
    for (int ks = 0; ks < NKS; ks++) {
        const uint32_t kb = ks * 32;
        uint32_t A[2][4], B[2][4];
#pragma unroll
        for (int mi = 0; mi < 2; mi++)
            LDSM4(A[mi], sb + SM_A + (warp_m + mi * 16) * ROWB + kb + offA);
#pragma unroll
        for (int nj = 0; nj < 2; nj++)
            LDSM4(B[nj], sb + SM_U + (warp_n + nj * 16) * ROWB + kb + offB);
#pragma unroll
        for (int mi = 0; mi < 2; mi++)
#pragma unroll
            for (int nj = 0; nj < 2; nj++)
#pragma unroll
                for (int hh = 0; hh < 2; hh++)
                    MMA16816(acc[mi][nj * 2 + hh],
                             A[mi][0], A[mi][1], A[mi][2], A[mi][3],
                             B[nj][hh * 2], B[nj][hh * 2 + 1]);
    }
}

// ---------- main: M=64/CTA, affine terms in-GEMM, 3 CTAs/SM ----------
__global__ __launch_bounds__(256, 3) void gru_main(
    const float* __restrict__ X, const float* __restrict__ hs,
    float* __restrict__ out_hnew, float* __restrict__ out_ht) {
    extern __shared__ __align__(16) unsigned char smem[];
    const uint32_t sb = smem_u32(smem);
    const int tid = threadIdx.x, warp = tid >> 5, l = tid & 31;
    const int i = blockIdx.y, b0 = blockIdx.x * MB;

    const unsigned char* uz = g_Uscr + (size_t)(0 * 256 + i) * (128 * SROWB);
    const unsigned char* ur = g_Uscr + (size_t)(1 * 256 + i) * (128 * SROWB);
    const unsigned char* uh = g_Uscr + (size_t)(2 * 256 + i) * (128 * SROWB);
    cp_u(sb + SM_U, uz, tid);

    // A body: fp16(hg), 64 rows x 16 chunks  (shifts only)
#pragma unroll
    for (int t = tid; t < 1024; t += 256) {
        uint32_t row = (uint32_t)t >> 4, ch = (uint32_t)t & 15u;
        int k0 = (int)ch * 8;
        const float4* g = (const float4*)(hs + (size_t)(b0 + row) * HD +
                                          (size_t)i * D_SZ + k0);
        float4 v0 = g[0], v1 = g[1];
        *(uint4*)(smem + SM_A + row * ROWB + ch * 16) =
            make_uint4(packh(v0.x, v0.y), packh(v0.z, v0.w),
                       packh(v1.x, v1.y), packh(v1.z, v1.w));
    }
    // A tail: chunk 16 = {x, 1, 0...}, chunk 17 = zeros
    if (tid < 128) {
        uint32_t row = (uint32_t)tid >> 1;
        if (tid & 1) {
            *(uint4*)(smem + SM_A + row * ROWB + 272) = make_uint4(0u, 0u, 0u, 0u);
        } else {
            float xv = X[(size_t)(b0 + row) * I_SZ + i];
            *(uint4*)(smem + SM_A + row * ROWB + 256) =
                make_uint4(packh(xv, 1.0f), 0u, 0u, 0u);
        }
    }
    CP_WAIT(0);
    __syncthreads();             // [1] A + Uz resident

    const int warp_m = (warp & 1) * 32, warp_n = (warp >> 1) * 32;
    const uint32_t offA = (uint32_t)((l & 15) * ROWB + (l >> 4) * 16);
    const uint32_t offB = (uint32_t)((l & 7) * ROWB + ((l >> 4) & 1) * (8 * ROWB) +
                                     ((l >> 3) & 1) * 16);
    float acc[2][4][4];
    half2 z2[2][4][2];           // z gate packed fp16 (8 regs)

    // ---- z gate ----
    gemm1(sb, warp_m, warp_n, offA, offB, acc);
    __syncthreads();             // [2] Uz reads done
    cp_u(sb + SM_U, ur, tid);    // Ur -> U, overlaps z epilogue
#pragma unroll
    for (int mi = 0; mi < 2; mi++)
#pragma unroll
        for (int j = 0; j < 4; j++)
#pragma unroll
            for (int rr = 0; rr < 2; rr++)
                z2[mi][j][rr] = __floats2half2_rn(sigf(acc[mi][j][rr * 2]),
                                                  sigf(acc[mi][j][rr * 2 + 1]));
    CP_WAIT(0);
    __syncthreads();             // [3] Ur resident

    // ---- r gate ----
    gemm1(sb, warp_m, warp_n, offA, offB, acc);
    __syncthreads();             // [4] Ur + A reads done
    cp_u(sb + SM_U, uh, tid);    // Uh -> U, overlaps r epilogue
#pragma unroll
    for (int mi = 0; mi < 2; mi++)
#pragma unroll
        for (int j = 0; j < 4; j++) {
            int col = warp_n + j * 8 + (l & 3) * 2;
#pragma unroll
            for (int rr = 0; rr < 2; rr++) {
                int row = warp_m + mi * 16 + rr * 8 + (l >> 2);
                half2* pA = (half2*)(smem + SM_A + row * ROWB + col * 2);
                half2 hg2 = *pA;
                float r0 = sigf(acc[mi][j][rr * 2]);
                float r1 = sigf(acc[mi][j][rr * 2 + 1]);
                *pA = __halves2half2(
                    __float2half_rn(r0 * __half2float(__low2half(hg2))),
                    __float2half_rn(r1 * __half2float(__high2half(hg2))));
            }
        }
    CP_WAIT(0);
    __syncthreads();             // [5] Uh + rh plane ready (x,1 cols untouched)

    // ---- h gate + fused combine (tail: global hg via __ldg, no barrier) ----
    gemm1(sb, warp_m, warp_n, offA, offB, acc);
#pragma unroll
    for (int mi = 0; mi < 2; mi++)
#pragma unroll
        for (int j = 0; j < 4; j++) {
            int col = warp_n + j * 8 + (l & 3) * 2;
#pragma unroll
            for (int rr = 0; rr < 2; rr++) {
                int row = warp_m + mi * 16 + rr * 8 + (l >> 2);
                size_t gidx = (size_t)(b0 + row) * HD + (size_t)i * D_SZ + col;
                float2 hg = __ldg((const float2*)(hs + gidx));
                float t0 = tanha(acc[mi][j][rr * 2]);
                float t1 = tanha(acc[mi][j][rr * 2 + 1]);
                float z0 = __half2float(__low2half(z2[mi][j][rr]));
                float z1 = __half2float(__high2half(z2[mi][j][rr]));
                *(float2*)(out_ht + gidx)   = make_float2(t0, t1);
                *(float2*)(out_hnew + gidx) = make_float2(z0 * hg.x + (1.0f - z0) * t0,
                                                          z1 * hg.y + (1.0f - z1) * t1);
            }
        }
}

extern "C" void kernel_launch(void* const* d_in, const int* in_sizes, int n_in,
                              void* d_out, int out_size) {
    const float* X  = (const float*)d_in[0];
    const float* h  = (const float*)d_in[1];
    const float* Wr = (const float*)d_in[2];
    const float* Wz = (const float*)d_in[3];
    const float* Wh = (const float*)d_in[4];
    const float* Ur = (const float*)d_in[5];
    const float* Uz = (const float*)d_in[6];
    const float* Uh = (const float*)d_in[7];
    const float* br = (const float*)d_in[8];
    const float* bz = (const float*)d_in[9];
    const float* bh = (const float*)d_in[10];
    float* out = (float*)d_out;
    float* out_hnew = out;
    float* out_ht   = out + (size_t)1024 * HD;

    cudaFuncSetAttribute(gru_prep, cudaFuncAttributeMaxDynamicSharedMemorySize, 128 * 129 * 4);
    cudaFuncSetAttribute(gru_main, cudaFuncAttributeMaxDynamicSharedMemorySize, (int)SMEM_MAIN);

    gru_prep<<<dim3(256, 3), 256, 128 * 129 * 4>>>(Uz, Ur, Uh, Wz, Wr, Wh, bz, br, bh);
    gru_main<<<dim3(16, 256), 256, SMEM_MAIN>>>(X, h, out_hnew, out_ht);
}